// round 16
// baseline (speedup 1.0000x reference)
#include <cuda_runtime.h>
#include <cuda_fp16.h>
#include <cstdint>
#include <math.h>

// ---------------- problem constants ----------------
#define BATCH    16384
#define F_IN     768
#define F_OUT    512
#define BM       64            // batch rows per unit
#define BN       256           // output cols per unit (n-half)
#define BK       64            // K chunk
#define NCHUNK   (F_IN / BK)   // 12 chunks per unit
#define NTHREADS 512
#define NCTA     148           // persistent CTAs
#define NUNITS   1024          // 256 m-tiles x 2 passes x 2 n-halves

// ---------------- smem layout (bytes) ----------------
#define SM_RED   0                     // 64 f32
#define SM_A0    4096                  // 2 stages x 8192 (64 rows x 128B)
#define SM_B     20480                 // 2 stages x 32768 (256 rows x 128B)
#define SM_TOTAL (SM_B + 2 * 32768)    // 86016

// ---------------- helpers ----------------
__device__ __forceinline__ uint32_t smem_u32(const void* p) {
    uint32_t a;
    asm("{ .reg .u64 t; cvta.to.shared.u64 t, %1; cvt.u32.u64 %0, t; }" : "=r"(a) : "l"(p));
    return a;
}

#define LDSM_X4(r0, r1, r2, r3, addr) \
    asm volatile("ldmatrix.sync.aligned.m8n8.x4.shared.b16 {%0,%1,%2,%3}, [%4];" \
                 : "=r"(r0), "=r"(r1), "=r"(r2), "=r"(r3) : "r"(addr))

#define MMA16816(d, a, b) \
    asm volatile("mma.sync.aligned.m16n8k16.row.col.f32.f16.f16.f32 " \
                 "{%0,%1,%2,%3}, {%4,%5,%6,%7}, {%8,%9}, {%0,%1,%2,%3};" \
                 : "+f"((d)[0]), "+f"((d)[1]), "+f"((d)[2]), "+f"((d)[3]) \
                 : "r"((a)[0]), "r"((a)[1]), "r"((a)[2]), "r"((a)[3]), \
                   "r"((b)[0]), "r"((b)[1]))

#define CP_ASYNC16(dst, src) \
    asm volatile("cp.async.cg.shared.global [%0], [%1], 16;" :: "r"(dst), "l"(src) : "memory")
#define CP_COMMIT() asm volatile("cp.async.commit_group;" ::: "memory")
#define CP_WAIT0()  asm volatile("cp.async.wait_group 0;" ::: "memory")

// cvt 8 f32 -> 8 f16, one swizzled 16B STS
__device__ __forceinline__ void sts_a16(uint32_t addr, float4 v0, float4 v1) {
    uint32_t u0, u1, u2, u3;
    asm("cvt.rn.f16x2.f32 %0, %1, %2;" : "=r"(u0) : "f"(v0.y), "f"(v0.x));
    asm("cvt.rn.f16x2.f32 %0, %1, %2;" : "=r"(u1) : "f"(v0.w), "f"(v0.z));
    asm("cvt.rn.f16x2.f32 %0, %1, %2;" : "=r"(u2) : "f"(v1.y), "f"(v1.x));
    asm("cvt.rn.f16x2.f32 %0, %1, %2;" : "=r"(u3) : "f"(v1.w), "f"(v1.z));
    asm volatile("st.shared.v4.u32 [%0], {%1,%2,%3,%4};"
                 :: "r"(addr), "r"(u0), "r"(u1), "r"(u2), "r"(u3) : "memory");
}

// ---------------- device globals ----------------
__device__ __align__(16) __half g_W1h[F_OUT * F_IN];
__device__ float g_part[4][BATCH];   // [pass*2 + nhalf][row], written once per launch

__global__ void __launch_bounds__(512) convert_w1_kernel(const float* __restrict__ W1) {
    const int base = blockIdx.x * 2048 + threadIdx.x;
    float4 v0 = reinterpret_cast<const float4*>(W1)[base];
    float4 v1 = reinterpret_cast<const float4*>(W1)[base + 512];
    float4 v2 = reinterpret_cast<const float4*>(W1)[base + 1024];
    float4 v3 = reinterpret_cast<const float4*>(W1)[base + 1536];
    __half2* dst = reinterpret_cast<__half2*>(g_W1h);
    dst[(base)        * 2]     = __floats2half2_rn(v0.x, v0.y);
    dst[(base)        * 2 + 1] = __floats2half2_rn(v0.z, v0.w);
    dst[(base + 512)  * 2]     = __floats2half2_rn(v1.x, v1.y);
    dst[(base + 512)  * 2 + 1] = __floats2half2_rn(v1.z, v1.w);
    dst[(base + 1024) * 2]     = __floats2half2_rn(v2.x, v2.y);
    dst[(base + 1024) * 2 + 1] = __floats2half2_rn(v2.z, v2.w);
    dst[(base + 1536) * 2]     = __floats2half2_rn(v3.x, v3.y);
    dst[(base + 1536) * 2 + 1] = __floats2half2_rn(v3.z, v3.w);
}

__global__ void __launch_bounds__(256) finalize_kernel(const float* __restrict__ b2,
                                                       float* __restrict__ out) {
    const int i = blockIdx.x * 256 + threadIdx.x;
    const float z = g_part[0][i] + g_part[1][i] + g_part[2][i] + g_part[3][i] + b2[0];
    out[i] = 1.0f / (1.0f + expf(-z));
}

// unit decode: uid = m*4 + pass*2 + nh
#define U_M0(uid)   (((uid) >> 2) * BM)
#define U_PASS(uid) (((uid) >> 1) & 1)
#define U_NH(uid)   ((uid) & 1)

// ---------------- persistent fused perspective-network kernel ----------------
// 148 CTAs x 512 threads (16 warps: warpM = wid>>3, warpN = wid&7; warp tile 32x32).
// Each CTA runs 6-7 units of (m-tile, pass, n-half), 12 chunks each, with a FLAT
// double-buffered cp.async pipeline across unit boundaries.
__global__ void __launch_bounds__(NTHREADS, 1)
persp_kernel(const float* __restrict__ stm, const float* __restrict__ nstm,
             const float* __restrict__ b1, const float* __restrict__ W2) {
    extern __shared__ __align__(1024) char smem[];
    const uint32_t sb = smem_u32(smem);
    const int tid  = threadIdx.x;
    const int lane = tid & 31;
    const int wid  = tid >> 5;
    const int warpM = wid >> 3;    // 0..1 (32 rows)
    const int warpN = wid & 7;     // 0..7 (32 cols)
    const int cta  = blockIdx.x;

    const int rem = NUNITS - (NUNITS / NCTA) * NCTA;   // 1024 - 6*148 = 136
    const int myUnits = (cta < rem) ? (NUNITS / NCTA + 1) : (NUNITS / NCTA);
    const int nT = myUnits * NCHUNK;

    float* red_s = reinterpret_cast<float*>(smem + SM_RED);
    if (tid < BM) red_s[tid] = 0.0f;

    // ---- ldmatrix per-lane geometry ----
    const int aRow   = warpM * 32 + ((lane >> 3) & 1) * 8 + (lane & 7);
    const uint32_t aXor = ((uint32_t)(lane >> 4) * 16) ^ ((uint32_t)(aRow & 7) << 4);
    const uint32_t aOff = aRow * 128;
    const int bRow   = warpN * 32 + ((lane >> 4) & 1) * 8 + (lane & 7);
    const uint32_t bXor = (((uint32_t)(lane >> 3) & 1) * 16) ^ ((uint32_t)(bRow & 7) << 4);
    const uint32_t bOff = bRow * 128;

    // ---- fill geometry ----
    // A: 64 rows x 64 f32; thread -> row tid>>3, 8 floats at (tid&7)*8
    const int aRowG = tid >> 3;
    const int aSeg  = tid & 7;
    const uint32_t aSts = aRowG * 128 + (((uint32_t)aSeg * 16) ^ ((uint32_t)(aRowG & 7) << 4));
    // B: 256 rows x 64 f16; thread -> rows (tid>>3)+64j (j<4), 16B seg tid&7
    const int bRow0 = tid >> 3;            // 0..63
    const int bSeg  = tid & 7;
    const uint32_t bDstSw = (((uint32_t)bSeg * 16) ^ ((uint32_t)(bRow0 & 7) << 4));

    float acc[2][4][4] = {};
    float rowsum[4] = {0.f, 0.f, 0.f, 0.f};
    float4 sA0, sA1;   // staged A regs (8 floats) for chunk t+1 at loop head

    // ---- prologue: fill stage0 with (unit0, chunk0); stage A for (unit0, chunk1) ----
    {
        const int uid0 = cta;
        const float* X0 = U_PASS(uid0) ? nstm : stm;
        const int m00 = U_M0(uid0), nh0 = U_NH(uid0);
        const __half* bs = g_W1h + (size_t)(nh0 * BN + bRow0) * F_IN + bSeg * 8;
#pragma unroll
        for (int j = 0; j < 4; ++j)
            CP_ASYNC16(sb + SM_B + (uint32_t)(bRow0 + 64 * j) * 128 + bDstSw,
                       bs + (size_t)(64 * j) * F_IN);
        CP_COMMIT();
        const float4* s0 = reinterpret_cast<const float4*>(
            X0 + (size_t)(m00 + aRowG) * F_IN + aSeg * 8);
        sts_a16(sb + SM_A0 + aSts, s0[0], s0[1]);
        const float4* s1 = reinterpret_cast<const float4*>(
            X0 + (size_t)(m00 + aRowG) * F_IN + BK + aSeg * 8);
        sA0 = s1[0]; sA1 = s1[1];
        CP_WAIT0();
        __syncthreads();
    }

    // flat-stream counters: (k, c) for current, +1 (prefetch), +2 (A staging)
    int k0 = 0, c0 = 0;
    int k1 = 0, c1 = 1;
    int k2 = 0, c2 = 2;

    for (int t = 0; t < nT; ++t) {
        const int p = t & 1;
        const uint32_t bufA  = sb + SM_A0 + p * 8192;
        const uint32_t bufB  = sb + SM_B  + p * 32768;
        const uint32_t bufAn = sb + SM_A0 + (p ^ 1) * 8192;
        const uint32_t bufBn = sb + SM_B  + (p ^ 1) * 32768;

        // ---- prefetch chunk t+1 (unit k1, chunk c1) ----
        if (t + 1 < nT) {
            sts_a16(bufAn + aSts, sA0, sA1);
            const int nh1 = U_NH(cta + k1 * NCTA);
            const __half* src = g_W1h + (size_t)(nh1 * BN + bRow0) * F_IN + c1 * BK + bSeg * 8;
#pragma unroll
            for (int j = 0; j < 4; ++j)
                CP_ASYNC16(bufBn + (uint32_t)(bRow0 + 64 * j) * 128 + bDstSw,
                           src + (size_t)(64 * j) * F_IN);
            CP_COMMIT();
        }
        // ---- stage A LDG for chunk t+2 (unit k2, chunk c2) ----
        if (t + 2 < nT) {
            const int uid2 = cta + k2 * NCTA;
            const float* X = U_PASS(uid2) ? nstm : stm;
            const float4* s = reinterpret_cast<const float4*>(
                X + (size_t)(U_M0(uid2) + aRowG) * F_IN + c2 * BK + aSeg * 8);
            sA0 = s[0]; sA1 = s[1];
        }

        // ---- compute chunk t ----
#pragma unroll
        for (int ks = 0; ks < 4; ++ks) {
            const uint32_t kx = (uint32_t)(ks << 5);
            uint32_t a0[4], a1[4];
            LDSM_X4(a0[0], a0[1], a0[2], a0[3], bufA + aOff +        (aXor ^ kx));
            LDSM_X4(a1[0], a1[1], a1[2], a1[3], bufA + aOff + 2048 + (aXor ^ kx));
            uint32_t b[4][2];
            {
                uint32_t r0, r1, r2, r3;
                LDSM_X4(r0, r1, r2, r3, bufB + bOff +        (bXor ^ kx));
                b[0][0] = r0; b[0][1] = r1; b[1][0] = r2; b[1][1] = r3;
                LDSM_X4(r0, r1, r2, r3, bufB + bOff + 2048 + (bXor ^ kx));
                b[2][0] = r0; b[2][1] = r1; b[3][0] = r2; b[3][1] = r3;
            }
#pragma unroll
            for (int nt = 0; nt < 4; ++nt) {
                MMA16816(acc[0][nt], a0, b[nt]);
                MMA16816(acc[1][nt], a1, b[nt]);
            }
        }

        // ---- unit boundary: epilogue + partial write ----
        if (c0 == NCHUNK - 1) {
            const int uid = cta + k0 * NCTA;
            const int m0 = U_M0(uid), pass = U_PASS(uid), nh = U_NH(uid);
            const int w2o = pass * F_OUT;
            const int nbase = nh * BN;
#pragma unroll
            for (int mt = 0; mt < 2; ++mt) {
#pragma unroll
                for (int nt = 0; nt < 4; ++nt) {
                    const int gn = nbase + warpN * 32 + nt * 8 + (lane & 3) * 2;
                    const float2 bv = __ldg(reinterpret_cast<const float2*>(b1 + gn));
                    const float2 wv = __ldg(reinterpret_cast<const float2*>(W2 + w2o + gn));
                    float h;
                    h = fminf(fmaxf(acc[mt][nt][0] + bv.x, 0.f), 1.f); rowsum[mt*2+0] = fmaf(h, wv.x, rowsum[mt*2+0]);
                    h = fminf(fmaxf(acc[mt][nt][1] + bv.y, 0.f), 1.f); rowsum[mt*2+0] = fmaf(h, wv.y, rowsum[mt*2+0]);
                    h = fminf(fmaxf(acc[mt][nt][2] + bv.x, 0.f), 1.f); rowsum[mt*2+1] = fmaf(h, wv.x, rowsum[mt*2+1]);
                    h = fminf(fmaxf(acc[mt][nt][3] + bv.y, 0.f), 1.f); rowsum[mt*2+1] = fmaf(h, wv.y, rowsum[mt*2+1]);
                    acc[mt][nt][0] = 0.f; acc[mt][nt][1] = 0.f;
                    acc[mt][nt][2] = 0.f; acc[mt][nt][3] = 0.f;
                }
            }
#pragma unroll
            for (int r = 0; r < 4; ++r) {
                float v = rowsum[r];
                v += __shfl_xor_sync(0xFFFFFFFFu, v, 1);
                v += __shfl_xor_sync(0xFFFFFFFFu, v, 2);
                if ((lane & 3) == 0) {
                    const int row = warpM * 32 + (r >> 1) * 16 + (r & 1) * 8 + (lane >> 2);
                    atomicAdd(&red_s[row], v);
                }
                rowsum[r] = 0.f;
            }
            __syncthreads();
            if (tid < BM) {
                const float v = red_s[tid];
                red_s[tid] = 0.0f;
                g_part[pass * 2 + nh][m0 + tid] = v;
            }
        }

        CP_WAIT0();
        __syncthreads();

        if (++c0 == NCHUNK) { c0 = 0; ++k0; }
        if (++c1 == NCHUNK) { c1 = 0; ++k1; }
        if (++c2 == NCHUNK) { c2 = 0; ++k2; }
    }
}

// ---------------- launch ----------------
extern "C" void kernel_launch(void* const* d_in, const int* in_sizes, int n_in,
                              void* d_out, int out_size) {
    const float* stm  = (const float*)d_in[0];
    const float* nstm = (const float*)d_in[1];
    const float* W1   = (const float*)d_in[2];
    const float* b1   = (const float*)d_in[3];
    const float* W2   = (const float*)d_in[4];
    const float* b2   = (const float*)d_in[5];
    float* out = (float*)d_out;

    cudaFuncSetAttribute(persp_kernel, cudaFuncAttributeMaxDynamicSharedMemorySize, SM_TOTAL);

    convert_w1_kernel<<<48, 512>>>(W1);
    persp_kernel<<<NCTA, NTHREADS, SM_TOTAL>>>(stm, nstm, b1, W2);
    finalize_kernel<<<BATCH / 256, 256>>>(b2, out);
}

// round 17
// speedup vs baseline: 1.1158x; 1.1158x over previous
#include <cuda_runtime.h>
#include <cuda_fp16.h>
#include <cstdint>
#include <math.h>

// ---------------- problem constants ----------------
#define BATCH    16384
#define F_IN     768
#define F_OUT    512
#define BM       64            // batch rows per CTA
#define BK       64            // K chunk
#define NCHUNK   (F_IN / BK)   // 12 chunks per pass
#define NPASS    2
#define TOTCHUNK (NCHUNK * NPASS)  // 24
#define NTHREADS 512
#define CTAS     (BATCH / BM)  // 256
#define NCONV    128           // converter CTAs (all within deterministic wave 1 of 148)

// ---------------- smem layout (bytes) ----------------
#define SM_BIAS  0                     // 512 f32 = 2048
#define SM_W2    2048                  // 1024 f32 = 4096
#define SM_RED   6144                  // 64 f32 = 256
#define SM_A0    8192                  // 64 rows x 128B = 8192
#define SM_A1    16384
#define SM_B0    24576                 // 512 rows x 128B = 65536
#define SM_B1    90112
#define SM_TOTAL 155648

// ---------------- helpers ----------------
__device__ __forceinline__ uint32_t smem_u32(const void* p) {
    uint32_t a;
    asm("{ .reg .u64 t; cvta.to.shared.u64 t, %1; cvt.u32.u64 %0, t; }" : "=r"(a) : "l"(p));
    return a;
}

#define LDSM_X4(r0, r1, r2, r3, addr) \
    asm volatile("ldmatrix.sync.aligned.m8n8.x4.shared.b16 {%0,%1,%2,%3}, [%4];" \
                 : "=r"(r0), "=r"(r1), "=r"(r2), "=r"(r3) : "r"(addr))

#define MMA16816(d, a, b) \
    asm volatile("mma.sync.aligned.m16n8k16.row.col.f32.f16.f16.f32 " \
                 "{%0,%1,%2,%3}, {%4,%5,%6,%7}, {%8,%9}, {%0,%1,%2,%3};" \
                 : "+f"((d)[0]), "+f"((d)[1]), "+f"((d)[2]), "+f"((d)[3]) \
                 : "r"((a)[0]), "r"((a)[1]), "r"((a)[2]), "r"((a)[3]), \
                   "r"((b)[0]), "r"((b)[1]))

#define CP_ASYNC16(dst, src) \
    asm volatile("cp.async.cg.shared.global [%0], [%1], 16;" :: "r"(dst), "l"(src) : "memory")
#define CP_COMMIT() asm volatile("cp.async.commit_group;" ::: "memory")
#define CP_WAIT0()  asm volatile("cp.async.wait_group 0;" ::: "memory")

// cvt 8 f32 -> 8 f16, one swizzled 16B STS
__device__ __forceinline__ void sts_a16(uint32_t addr, float4 v0, float4 v1) {
    uint32_t u0, u1, u2, u3;
    asm("cvt.rn.f16x2.f32 %0, %1, %2;" : "=r"(u0) : "f"(v0.y), "f"(v0.x));
    asm("cvt.rn.f16x2.f32 %0, %1, %2;" : "=r"(u1) : "f"(v0.w), "f"(v0.z));
    asm("cvt.rn.f16x2.f32 %0, %1, %2;" : "=r"(u2) : "f"(v1.y), "f"(v1.x));
    asm("cvt.rn.f16x2.f32 %0, %1, %2;" : "=r"(u3) : "f"(v1.w), "f"(v1.z));
    asm volatile("st.shared.v4.u32 [%0], {%1,%2,%3,%4};"
                 :: "r"(addr), "r"(u0), "r"(u1), "r"(u2), "r"(u3) : "memory");
}

// ---------------- device globals ----------------
__device__ __align__(16) __half g_W1h[F_OUT * F_IN];
__device__ unsigned int g_convDone = 0;   // monotonic: +NCONV per replay
__device__ unsigned int g_arrivals = 0;   // monotonic: +CTAS per replay

// ---------------- fused perspective-network kernel (R4 body + in-kernel W1 convert) ----------------
// 16 warps: warpM = wid>>3 (2 x 32 rows), warpN = wid&7 (8 x 64 cols).
__global__ void __launch_bounds__(NTHREADS, 1)
persp_kernel(const float* __restrict__ stm, const float* __restrict__ nstm,
             const float* __restrict__ W1, const float* __restrict__ b1,
             const float* __restrict__ W2, const float* __restrict__ b2,
             float* __restrict__ out) {
    extern __shared__ __align__(1024) char smem[];
    const uint32_t sb = smem_u32(smem);
    const int tid  = threadIdx.x;
    const int lane = tid & 31;
    const int wid  = tid >> 5;
    const int warpM = wid >> 3;    // 0..1
    const int warpN = wid & 7;     // 0..7
    const int m0 = blockIdx.x * BM;

    // ================= one-shot W1 fp32->fp16 conversion, replay-safe =================
    // CTAs 0..NCONV-1 convert slices; ALL CTAs wait on a monotonic counter.
    // Epoch derived from a monotonic arrival counter (>>8 since CTAS=256).
    if (blockIdx.x < NCONV) {
        // slice: 98304 float4 / 128 CTAs = 768 float4 per CTA
        const int base = blockIdx.x * 768;
        for (int i = tid; i < 768; i += NTHREADS) {
            float4 v = reinterpret_cast<const float4*>(W1)[base + i];
            __half2* dst = reinterpret_cast<__half2*>(g_W1h) + (size_t)(base + i) * 2;
            dst[0] = __floats2half2_rn(v.x, v.y);
            dst[1] = __floats2half2_rn(v.z, v.w);
        }
        __syncthreads();
        if (tid == 0) {
            __threadfence();
            atomicAdd(&g_convDone, 1u);
        }
    }
    if (tid == 0) {
        const unsigned int old_e = atomicAdd(&g_arrivals, 1u);
        const unsigned int target = ((old_e >> 8) + 1u) * (unsigned)NCONV;
        while (atomicAdd(&g_convDone, 0u) < target) { }
        __threadfence();
    }
    __syncthreads();   // all threads ordered after the wait

    float* bias_s = reinterpret_cast<float*>(smem + SM_BIAS);
    float* w2_s   = reinterpret_cast<float*>(smem + SM_W2);
    float* red_s  = reinterpret_cast<float*>(smem + SM_RED);

    for (int i = tid; i < F_OUT; i += NTHREADS)     bias_s[i] = b1[i];
    for (int i = tid; i < 2 * F_OUT; i += NTHREADS) w2_s[i]   = W2[i];
    if (tid < BM) red_s[tid] = 0.0f;

    // ---- ldmatrix per-lane geometry ----
    const int aRow   = warpM * 32 + ((lane >> 3) & 1) * 8 + (lane & 7);
    const uint32_t aXor = ((uint32_t)(lane >> 4) * 16) ^ ((uint32_t)(aRow & 7) << 4);
    const uint32_t aOff = aRow * 128;
    const int bRow   = warpN * 64 + ((lane >> 4) & 1) * 8 + (lane & 7);
    const uint32_t bXor = (((uint32_t)(lane >> 3) & 1) * 16) ^ ((uint32_t)(bRow & 7) << 4);
    const uint32_t bOff = bRow * 128;

    // ---- global->smem fill geometry ----
    const int aRowG = tid >> 3;             // 0..63
    const int aSeg  = tid & 7;              // 8-float segment
    const uint32_t aSts = aRowG * 128 + (((uint32_t)aSeg * 16) ^ ((uint32_t)(aRowG & 7) << 4));
    const int bRow0 = tid >> 3;             // 0..63, rows bRow0 + 64*j
    const int bSeg  = tid & 7;
    const uint32_t bDstBase = bRow0 * 128 + (((uint32_t)bSeg * 16) ^ ((uint32_t)(bRow0 & 7) << 4));
    const __half* bSrcBase = g_W1h + (size_t)bRow0 * F_IN + bSeg * 8;

    float acc[2][8][4] = {};
    float rowsum[4] = {0.f, 0.f, 0.f, 0.f};
    float4 sA0, sA1;   // staged A regs (chunk g+1)

    // ---- prologue: fill buf0 (chunk 0), stage A(chunk 1) ----
    {
        const uint32_t bufB = sb + SM_B0;
#pragma unroll
        for (int j = 0; j < 8; ++j)
            CP_ASYNC16(bufB + bDstBase + j * 8192, bSrcBase + (size_t)j * 64 * F_IN);
        CP_COMMIT();
        const float4* s0 = reinterpret_cast<const float4*>(
            stm + (size_t)(m0 + aRowG) * F_IN + aSeg * 8);
        sts_a16(sb + SM_A0 + aSts, s0[0], s0[1]);
        const float4* s1 = reinterpret_cast<const float4*>(
            stm + (size_t)(m0 + aRowG) * F_IN + 1 * BK + aSeg * 8);
        sA0 = s1[0]; sA1 = s1[1];
        CP_WAIT0();
        __syncthreads();
    }

    for (int g = 0; g < TOTCHUNK; ++g) {
        const int p = g & 1;
        const uint32_t bufA  = sb + (p ? SM_A1 : SM_A0);
        const uint32_t bufB  = sb + (p ? SM_B1 : SM_B0);
        const uint32_t bufAn = sb + (p ? SM_A0 : SM_A1);
        const uint32_t bufBn = sb + (p ? SM_B0 : SM_B1);

        // prefetch chunk g+1: staged A -> smem, B via cp.async
        if (g + 1 < TOTCHUNK) {
            sts_a16(bufAn + aSts, sA0, sA1);
            const int c1 = (g + 1) % NCHUNK;
            const __half* src = bSrcBase + c1 * BK;
#pragma unroll
            for (int j = 0; j < 8; ++j)
                CP_ASYNC16(bufBn + bDstBase + j * 8192, src + (size_t)j * 64 * F_IN);
            CP_COMMIT();
        }
        // LDG chunk g+2 into staging (lands during compute)
        if (g + 2 < TOTCHUNK) {
            const int g2 = g + 2;
            const float* X = (g2 >= NCHUNK) ? nstm : stm;
            const int c2 = g2 % NCHUNK;
            const float4* s = reinterpret_cast<const float4*>(
                X + (size_t)(m0 + aRowG) * F_IN + c2 * BK + aSeg * 8);
            sA0 = s[0]; sA1 = s[1];
        }

        // ---- compute chunk g from buf p ----
#pragma unroll
        for (int ks = 0; ks < 4; ++ks) {
            const uint32_t kx = (uint32_t)(ks << 5);
            uint32_t a0[4], a1[4];
            LDSM_X4(a0[0], a0[1], a0[2], a0[3], bufA + aOff +        (aXor ^ kx));
            LDSM_X4(a1[0], a1[1], a1[2], a1[3], bufA + aOff + 2048 + (aXor ^ kx));
            uint32_t b[8][2];
#pragma unroll
            for (int nt2 = 0; nt2 < 4; ++nt2) {
                uint32_t r0, r1, r2, r3;
                LDSM_X4(r0, r1, r2, r3, bufB + bOff + nt2 * 2048 + (bXor ^ kx));
                b[nt2 * 2][0] = r0; b[nt2 * 2][1] = r1;
                b[nt2 * 2 + 1][0] = r2; b[nt2 * 2 + 1][1] = r3;
            }
#pragma unroll
            for (int nt = 0; nt < 8; ++nt) {
                MMA16816(acc[0][nt], a0, b[nt]);
                MMA16816(acc[1][nt], a1, b[nt]);
            }
        }

        // ---- end-of-pass epilogue: bias + clip + W2 partial dot, reset acc ----
        if (g == NCHUNK - 1 || g == TOTCHUNK - 1) {
            const int pass = (g >= NCHUNK);
            const int w2o = pass * F_OUT;
#pragma unroll
            for (int mt = 0; mt < 2; ++mt) {
#pragma unroll
                for (int nt = 0; nt < 8; ++nt) {
                    const int nb = warpN * 64 + nt * 8 + (lane & 3) * 2;
                    const float ba = bias_s[nb],      bb = bias_s[nb + 1];
                    const float wa = w2_s[w2o + nb],  wb = w2_s[w2o + nb + 1];
                    float h;
                    h = fminf(fmaxf(acc[mt][nt][0] + ba, 0.f), 1.f); rowsum[mt*2+0] = fmaf(h, wa, rowsum[mt*2+0]);
                    h = fminf(fmaxf(acc[mt][nt][1] + bb, 0.f), 1.f); rowsum[mt*2+0] = fmaf(h, wb, rowsum[mt*2+0]);
                    h = fminf(fmaxf(acc[mt][nt][2] + ba, 0.f), 1.f); rowsum[mt*2+1] = fmaf(h, wa, rowsum[mt*2+1]);
                    h = fminf(fmaxf(acc[mt][nt][3] + bb, 0.f), 1.f); rowsum[mt*2+1] = fmaf(h, wb, rowsum[mt*2+1]);
                    acc[mt][nt][0] = 0.f; acc[mt][nt][1] = 0.f;
                    acc[mt][nt][2] = 0.f; acc[mt][nt][3] = 0.f;
                }
            }
        }

        CP_WAIT0();
        __syncthreads();
    }

    // ---- cross-lane + cross-warp reduce, sigmoid, store ----
#pragma unroll
    for (int r = 0; r < 4; ++r) {
        float v = rowsum[r];
        v += __shfl_xor_sync(0xFFFFFFFFu, v, 1);
        v += __shfl_xor_sync(0xFFFFFFFFu, v, 2);
        if ((lane & 3) == 0) {
            const int row = warpM * 32 + (r >> 1) * 16 + (r & 1) * 8 + (lane >> 2);
            atomicAdd(&red_s[row], v);
        }
    }
    __syncthreads();
    if (tid < BM) {
        const float z = red_s[tid] + b2[0];
        out[m0 + tid] = 1.0f / (1.0f + expf(-z));
    }
}

// ---------------- launch ----------------
extern "C" void kernel_launch(void* const* d_in, const int* in_sizes, int n_in,
                              void* d_out, int out_size) {
    const float* stm  = (const float*)d_in[0];
    const float* nstm = (const float*)d_in[1];
    const float* W1   = (const float*)d_in[2];
    const float* b1   = (const float*)d_in[3];
    const float* W2   = (const float*)d_in[4];
    const float* b2   = (const float*)d_in[5];
    float* out = (float*)d_out;

    cudaFuncSetAttribute(persp_kernel, cudaFuncAttributeMaxDynamicSharedMemorySize, SM_TOTAL);
    persp_kernel<<<CTAS, NTHREADS, SM_TOTAL>>>(stm, nstm, W1, b1, W2, b2, out);
}